// round 16
// baseline (speedup 1.0000x reference)
#include <cuda_runtime.h>
#include <cuda_fp16.h>
#include <cstdint>
#include <cstddef>

// Problem constants
#define BB   512
#define AA   100
#define HH   1024
#define INN  77          // S*T = 7*11
#define KPAD 128         // padded input-feature dim
#define GG   4096        // 4*H
#define M1   (AA*BB)     // 51200
#define BH   (BB*HH)     // 524288

#define NBLK 256         // persistent grid size (32 x 8)
#define NTHR 128

// ---------------- scratch (device globals; no allocation allowed) ----------------
__device__ __half g_xh    [(size_t)M1 * KPAD];   // reordered+padded inputs (fp16)
__device__ __half g_wembT [(size_t)KPAD * HH];   // W_emb^T padded (fp16)
__device__ __half g_wih_h [(size_t)GG * HH];     // W_ih fp16 (for Wc GEMM)
__device__ __half g_wc    [(size_t)GG * KPAD];   // Wc = W_ih @ W_emb  (fp16)
__device__ float  g_bias_c[GG];                  // W_ih@b_emb + b_ih + b_hh (fp32)
__device__ __half g_gx    [(size_t)M1 * GG];     // precomputed input gates (fp16)
__device__ float  g_ghf   [(size_t)BB * GG];     // recurrent gates (fp32)
__device__ __half g_hf    [BH];                  // h state (fp16)
__device__ float  g_c     [BH];                  // c state (fp32)
__device__ __half g_whh   [(size_t)GG * HH];     // Whh fp16
__device__ unsigned g_barc;                      // grid barrier: arrival count
__device__ unsigned g_barg;                      // grid barrier: generation

// ================= PTX helpers (sm_80+ standard; NO arch-'a' features) =========
__device__ __forceinline__ uint32_t smem_u32(const void* p) {
    uint32_t a;
    asm("{ .reg .u64 t; cvta.to.shared.u64 t, %1; cvt.u32.u64 %0, t; }" : "=r"(a) : "l"(p));
    return a;
}
#define SMEM_SWIZZLE_128B(o) ((o) ^ (((o) >> 3) & 0x70))

__device__ __forceinline__ void cp_async16(uint32_t smem_addr, const void* gptr) {
    asm volatile("cp.async.cg.shared.global [%0], [%1], 16;"
                 :: "r"(smem_addr), "l"(gptr) : "memory");
}
#define CP_COMMIT() asm volatile("cp.async.commit_group;" ::: "memory")
#define CP_WAIT(n)  asm volatile("cp.async.wait_group %0;" :: "n"(n) : "memory")

__device__ __forceinline__ void ldsm_x4(uint32_t addr, uint32_t& r0, uint32_t& r1,
                                        uint32_t& r2, uint32_t& r3) {
    asm volatile("ldmatrix.sync.aligned.m8n8.x4.shared.b16 {%0,%1,%2,%3}, [%4];"
                 : "=r"(r0), "=r"(r1), "=r"(r2), "=r"(r3) : "r"(addr));
}

__device__ __forceinline__ void mma_f16(float* d, const uint32_t* a, const uint32_t* b) {
    asm volatile(
        "mma.sync.aligned.m16n8k16.row.col.f32.f16.f16.f32 "
        "{%0,%1,%2,%3}, {%4,%5,%6,%7}, {%8,%9}, {%0,%1,%2,%3};"
        : "+f"(d[0]), "+f"(d[1]), "+f"(d[2]), "+f"(d[3])
        : "r"(a[0]), "r"(a[1]), "r"(a[2]), "r"(a[3]), "r"(b[0]), "r"(b[1]));
}

// Software grid barrier (all NBLK CTAs resident by resource construction).
__device__ __forceinline__ void grid_barrier() {
    __syncthreads();
    if (threadIdx.x == 0) {
        const unsigned gen = atomicAdd(&g_barg, 0u);   // read gen BEFORE arriving
        __threadfence();
        const unsigned t = atomicAdd(&g_barc, 1u);
        if (t == NBLK - 1) {
            g_barc = 0;
            __threadfence();
            atomicAdd(&g_barg, 1u);
        } else {
            while (atomicAdd(&g_barg, 0u) == gen) { __nanosleep(64); }
        }
        __threadfence();
    }
    __syncthreads();
}

// ================= prep kernels =================
__global__ void reorder_pad_kernel(const float* __restrict__ inputs) {
    int idx = blockIdx.x * blockDim.x + threadIdx.x;
    if (idx >= M1 * KPAD) return;
    int i = idx & (KPAD - 1);
    int r = idx >> 7;         // r = a*B + b
    int b = r % BB;
    int a = r / BB;
    float v = (i < INN) ? inputs[(size_t)b * (AA * INN) + (size_t)a * INN + i] : 0.f;
    g_xh[idx] = __float2half(v);
}

// W_emb [H,77] -> transposed+padded fp16 [128, H]
__global__ void transpose_wemb_kernel(const float* __restrict__ W_emb) {
    int idx = blockIdx.x * blockDim.x + threadIdx.x;
    if (idx >= KPAD * HH) return;
    int h = idx & (HH - 1);
    int n = idx >> 10;
    float v = (n < INN) ? W_emb[(size_t)h * INN + n] : 0.f;
    g_wembT[idx] = __float2half(v);
}

// bias_c[j] = dot(W_ih[j,:], b_emb) + b_ih[j] + b_hh[j]; one 128-thr block per j
__global__ void bias_c_kernel(const float* __restrict__ W_ih, const float* __restrict__ b_emb,
                              const float* __restrict__ b_ih, const float* __restrict__ b_hh) {
    __shared__ float red[4];
    const int j = blockIdx.x;
    const int tid = threadIdx.x;
    float s = 0.f;
    for (int h = tid; h < HH; h += 128)
        s += W_ih[(size_t)j * HH + h] * b_emb[h];
    #pragma unroll
    for (int o = 16; o > 0; o >>= 1) s += __shfl_down_sync(0xFFFFFFFFu, s, o);
    if ((tid & 31) == 0) red[tid >> 5] = s;
    __syncthreads();
    if (tid == 0)
        g_bias_c[j] = red[0] + red[1] + red[2] + red[3] + b_ih[j] + b_hh[j];
}

__global__ void state_init_kernel(const float* __restrict__ h0, const float* __restrict__ c0) {
    int i = blockIdx.x * blockDim.x + threadIdx.x;
    if (i == 0) { g_barc = 0; g_barg = 0; }   // reset barrier for graph replay
    if (i >= BH) return;
    g_hf[i] = __float2half(h0[i]);
    g_c[i] = c0[i];
}

__global__ void conv_f16_kernel(const float* __restrict__ src, __half* __restrict__ dst, int n) {
    int i = blockIdx.x * blockDim.x + threadIdx.x;
    if (i < n) dst[i] = __float2half(src[i]);
}

// ============== fp16 single-term GEMM, K-chunk 64 (R14/15-proven pipeline) =====
#define HCHUNK 64
#define A_TILE 8192                     // 64 rows * 128B
#define B_TILE 16384                    // 128 rows * 128B
#define F_STAGE (A_TILE + B_TILE)       // 24 KB
#define F_NSTAGE 3
#define SMEM_F_BYTES (F_NSTAGE * F_STAGE + 1024)

template<int EPI>   // 0 = float C, 1 = __half C
__global__ __launch_bounds__(128, 3)
void mma_gemm_h1(const __half* __restrict__ A, const __half* __restrict__ B,
                 const float* __restrict__ bias, void* __restrict__ Cv,
                 int K, int ldc) {
    extern __shared__ char sm[];
    const uint32_t base = (smem_u32(sm) + 1023u) & ~1023u;
    const int tid = threadIdx.x;
    const int wid = tid >> 5, lane = tid & 31;
    const int wn = wid * 32;

    const __half* A_b = A + (size_t)blockIdx.y * 64 * K;
    const __half* B_b = B + (size_t)blockIdx.x * 128 * K;

    const int nchunk = K / HCHUNK;

    float acc[4][4][4];
    #pragma unroll
    for (int mi = 0; mi < 4; mi++)
        #pragma unroll
        for (int nj = 0; nj < 4; nj++)
            #pragma unroll
            for (int q = 0; q < 4; q++) acc[mi][nj][q] = 0.f;

    auto prefetch = [&](int ch) {
        const int kc = ch * HCHUNK;
        const uint32_t st = base + (uint32_t)(ch % F_NSTAGE) * F_STAGE;
        #pragma unroll
        for (int it = 0; it < 4; it++) {
            const int idx = it * 128 + tid;
            const int row = idx >> 3;
            const int g   = idx & 7;
            const uint32_t off = SMEM_SWIZZLE_128B((uint32_t)(row * 128 + g * 16));
            cp_async16(st + off, A_b + (size_t)row * K + kc + g * 8);
        }
        #pragma unroll
        for (int it = 0; it < 8; it++) {
            const int idx = it * 128 + tid;
            const int row = idx >> 3;
            const int g   = idx & 7;
            const uint32_t off = SMEM_SWIZZLE_128B((uint32_t)(row * 128 + g * 16));
            cp_async16(st + A_TILE + off, B_b + (size_t)row * K + kc + g * 8);
        }
    };

    prefetch(0); CP_COMMIT();
    if (nchunk > 1) { prefetch(1); CP_COMMIT(); }

    const int tsel = lane >> 3, rin = lane & 7;

    for (int ch = 0; ch < nchunk; ch++) {
        if (ch + 2 < nchunk) {
            prefetch(ch + 2);
            CP_COMMIT();
            CP_WAIT(2);
        } else {
            CP_WAIT(0);
        }
        __syncthreads();

        const uint32_t st = base + (uint32_t)(ch % F_NSTAGE) * F_STAGE;
        const uint32_t sB = st + A_TILE;

        #pragma unroll
        for (int kk = 0; kk < HCHUNK; kk += 16) {
            const int colb = (kk + (tsel >> 1) * 8) * 2;
            uint32_t a[4][4];
            #pragma unroll
            for (int mi = 0; mi < 4; mi++) {
                const int row = mi * 16 + (tsel & 1) * 8 + rin;
                ldsm_x4(st + SMEM_SWIZZLE_128B((uint32_t)(row * 128 + colb)),
                        a[mi][0], a[mi][1], a[mi][2], a[mi][3]);
            }
            uint32_t b[4][2];
            #pragma unroll
            for (int g = 0; g < 2; g++) {
                const int row = wn + g * 16 + (tsel & 1) * 8 + rin;
                uint32_t r0, r1, r2, r3;
                ldsm_x4(sB + SMEM_SWIZZLE_128B((uint32_t)(row * 128 + colb)),
                        r0, r1, r2, r3);
                b[g * 2 + 0][0] = r0; b[g * 2 + 0][1] = r2;
                b[g * 2 + 1][0] = r1; b[g * 2 + 1][1] = r3;
            }
            #pragma unroll
            for (int mi = 0; mi < 4; mi++)
                #pragma unroll
                for (int nj = 0; nj < 4; nj++)
                    mma_f16(acc[mi][nj], a[mi], b[nj]);
        }
        __syncthreads();
    }

    const int r0 = lane >> 2;
    const int c0 = (lane & 3) * 2;
    #pragma unroll
    for (int mi = 0; mi < 4; mi++) {
        const size_t m0 = (size_t)blockIdx.y * 64 + mi * 16;
        #pragma unroll
        for (int nj = 0; nj < 4; nj++) {
            const int n = blockIdx.x * 128 + wn + nj * 8 + c0;
            float bx = 0.f, by = 0.f;
            if (bias) { bx = bias[n]; by = bias[n + 1]; }
            float vs[4] = {acc[mi][nj][0] + bx, acc[mi][nj][1] + by,
                           acc[mi][nj][2] + bx, acc[mi][nj][3] + by};
            if (EPI == 0) {
                float* C = (float*)Cv;
                *(float2*)(C + (m0 + r0) * (size_t)ldc + n) = make_float2(vs[0], vs[1]);
                *(float2*)(C + (m0 + r0 + 8) * (size_t)ldc + n) = make_float2(vs[2], vs[3]);
            } else {
                __half* C = (__half*)Cv;
                *(__half2*)(C + (m0 + r0) * (size_t)ldc + n) =
                    __floats2half2_rn(vs[0], vs[1]);
                *(__half2*)(C + (m0 + r0 + 8) * (size_t)ldc + n) =
                    __floats2half2_rn(vs[2], vs[3]);
            }
        }
    }
}

// ============== persistent recurrence kernel: 100 x (GEMM ; bar ; cell ; bar) ===
__global__ __launch_bounds__(128, 3)
void lstm_persistent(const __half* __restrict__ gx_all, float* __restrict__ out) {
    extern __shared__ char sm[];
    const uint32_t base = (smem_u32(sm) + 1023u) & ~1023u;
    const int tid = threadIdx.x;
    const int wid = tid >> 5, lane = tid & 31;
    const int wn = wid * 32;
    const int tsel = lane >> 3, rin = lane & 7;
    const int gtid = (blockIdx.y * 32 + blockIdx.x) * NTHR + tid;   // 0..32767

    const __half* B_b = g_whh + (size_t)blockIdx.x * 128 * HH;
    const __half* A_b = g_hf + (size_t)blockIdx.y * 64 * HH;
    const int nchunk = HH / HCHUNK;     // 16

    for (int t = 0; t < AA; t++) {
        // ---------------- GEMM phase: ghf = hf @ Whh^T ----------------
        float acc[4][4][4];
        #pragma unroll
        for (int mi = 0; mi < 4; mi++)
            #pragma unroll
            for (int nj = 0; nj < 4; nj++)
                #pragma unroll
                for (int q = 0; q < 4; q++) acc[mi][nj][q] = 0.f;

        auto prefetch = [&](int ch) {
            const int kc = ch * HCHUNK;
            const uint32_t st = base + (uint32_t)(ch % F_NSTAGE) * F_STAGE;
            #pragma unroll
            for (int it = 0; it < 4; it++) {
                const int idx = it * 128 + tid;
                const int row = idx >> 3;
                const int g   = idx & 7;
                const uint32_t off = SMEM_SWIZZLE_128B((uint32_t)(row * 128 + g * 16));
                cp_async16(st + off, A_b + (size_t)row * HH + kc + g * 8);
            }
            #pragma unroll
            for (int it = 0; it < 8; it++) {
                const int idx = it * 128 + tid;
                const int row = idx >> 3;
                const int g   = idx & 7;
                const uint32_t off = SMEM_SWIZZLE_128B((uint32_t)(row * 128 + g * 16));
                cp_async16(st + A_TILE + off, B_b + (size_t)row * HH + kc + g * 8);
            }
        };

        prefetch(0); CP_COMMIT();
        prefetch(1); CP_COMMIT();

        for (int ch = 0; ch < nchunk; ch++) {
            if (ch + 2 < nchunk) {
                prefetch(ch + 2);
                CP_COMMIT();
                CP_WAIT(2);
            } else {
                CP_WAIT(0);
            }
            __syncthreads();

            const uint32_t st = base + (uint32_t)(ch % F_NSTAGE) * F_STAGE;
            const uint32_t sB = st + A_TILE;

            #pragma unroll
            for (int kk = 0; kk < HCHUNK; kk += 16) {
                const int colb = (kk + (tsel >> 1) * 8) * 2;
                uint32_t a[4][4];
                #pragma unroll
                for (int mi = 0; mi < 4; mi++) {
                    const int row = mi * 16 + (tsel & 1) * 8 + rin;
                    ldsm_x4(st + SMEM_SWIZZLE_128B((uint32_t)(row * 128 + colb)),
                            a[mi][0], a[mi][1], a[mi][2], a[mi][3]);
                }
                uint32_t b[4][2];
                #pragma unroll
                for (int g = 0; g < 2; g++) {
                    const int row = wn + g * 16 + (tsel & 1) * 8 + rin;
                    uint32_t r0, r1, r2, r3;
                    ldsm_x4(sB + SMEM_SWIZZLE_128B((uint32_t)(row * 128 + colb)),
                            r0, r1, r2, r3);
                    b[g * 2 + 0][0] = r0; b[g * 2 + 0][1] = r2;
                    b[g * 2 + 1][0] = r1; b[g * 2 + 1][1] = r3;
                }
                #pragma unroll
                for (int mi = 0; mi < 4; mi++)
                    #pragma unroll
                    for (int nj = 0; nj < 4; nj++)
                        mma_f16(acc[mi][nj], a[mi], b[nj]);
            }
            __syncthreads();
        }

        // epilogue: ghf (fp32)
        {
            const int r0 = lane >> 2;
            const int c0 = (lane & 3) * 2;
            #pragma unroll
            for (int mi = 0; mi < 4; mi++) {
                const size_t m0 = (size_t)blockIdx.y * 64 + mi * 16;
                #pragma unroll
                for (int nj = 0; nj < 4; nj++) {
                    const int n = blockIdx.x * 128 + wn + nj * 8 + c0;
                    *(float2*)(g_ghf + (m0 + r0) * (size_t)GG + n) =
                        make_float2(acc[mi][nj][0], acc[mi][nj][1]);
                    *(float2*)(g_ghf + (m0 + r0 + 8) * (size_t)GG + n) =
                        make_float2(acc[mi][nj][2], acc[mi][nj][3]);
                }
            }
        }

        grid_barrier();

        // ---------------- cell phase (vectorized by 2) ----------------
        {
            const __half* gx = gx_all + (size_t)t * BB * GG;
            float* out_t = out + (size_t)t * BH;
            #pragma unroll
            for (int it = 0; it < BH / 2 / (NBLK * NTHR); it++) {
                const int p = it * (NBLK * NTHR) + gtid;     // pair index
                const int idx = p * 2;                       // element index (even)
                const int b = idx / HH, hh = idx % HH;
                const size_t gb = (size_t)b * GG;
                __half2 x0 = *(const __half2*)(gx + gb + hh);
                __half2 x1 = *(const __half2*)(gx + gb + HH + hh);
                __half2 x2 = *(const __half2*)(gx + gb + 2 * HH + hh);
                __half2 x3 = *(const __half2*)(gx + gb + 3 * HH + hh);
                float2 h0 = *(const float2*)(g_ghf + gb + hh);
                float2 h1 = *(const float2*)(g_ghf + gb + HH + hh);
                float2 h2 = *(const float2*)(g_ghf + gb + 2 * HH + hh);
                float2 h3 = *(const float2*)(g_ghf + gb + 3 * HH + hh);
                float2 cc = *(const float2*)(g_c + idx);
                float hn0, hn1, cn0, cn1;
                {
                    float gi = __low2float(x0) + h0.x;
                    float gf = __low2float(x1) + h1.x;
                    float gg = __low2float(x2) + h2.x;
                    float go = __low2float(x3) + h3.x;
                    float i = 1.f / (1.f + expf(-gi));
                    float f = 1.f / (1.f + expf(-gf));
                    float g = tanhf(gg);
                    float o = 1.f / (1.f + expf(-go));
                    cn0 = f * cc.x + i * g;
                    hn0 = o * tanhf(cn0);
                }
                {
                    float gi = __high2float(x0) + h0.y;
                    float gf = __high2float(x1) + h1.y;
                    float gg = __high2float(x2) + h2.y;
                    float go = __high2float(x3) + h3.y;
                    float i = 1.f / (1.f + expf(-gi));
                    float f = 1.f / (1.f + expf(-gf));
                    float g = tanhf(gg);
                    float o = 1.f / (1.f + expf(-go));
                    cn1 = f * cc.y + i * g;
                    hn1 = o * tanhf(cn1);
                }
                *(float2*)(g_c + idx) = make_float2(cn0, cn1);
                *(__half2*)(g_hf + idx) = __floats2half2_rn(hn0, hn1);
                *(float2*)(out_t + idx) = make_float2(hn0, hn1);
            }
        }

        grid_barrier();
    }
}

__global__ void copy_hc_kernel(const float* __restrict__ last_h, float* __restrict__ dst) {
    int i = blockIdx.x * blockDim.x + threadIdx.x;
    if (i < BH) { dst[i] = last_h[i]; dst[BH + i] = g_c[i]; }
}

// ---------------- launch ----------------
extern "C" void kernel_launch(void* const* d_in, const int* in_sizes, int n_in,
                              void* d_out, int out_size) {
    const float* inputs = (const float*)d_in[0];
    const float* h0     = (const float*)d_in[1];
    const float* c0     = (const float*)d_in[2];
    const float* W_emb  = (const float*)d_in[3];
    const float* b_emb  = (const float*)d_in[4];
    const float* W_ih   = (const float*)d_in[5];
    const float* W_hh   = (const float*)d_in[6];
    const float* b_ih   = (const float*)d_in[7];
    const float* b_hh   = (const float*)d_in[8];
    float* out = (float*)d_out;

    // Real device addresses of scratch globals (host-shadow trap otherwise).
    float *p_biasc;
    __half *p_xh, *p_wembT, *p_wih, *p_wc, *p_gx, *p_whh;
    cudaGetSymbolAddress((void**)&p_xh,    g_xh);
    cudaGetSymbolAddress((void**)&p_wembT, g_wembT);
    cudaGetSymbolAddress((void**)&p_wih,   g_wih_h);
    cudaGetSymbolAddress((void**)&p_wc,    g_wc);
    cudaGetSymbolAddress((void**)&p_biasc, g_bias_c);
    cudaGetSymbolAddress((void**)&p_gx,    g_gx);
    cudaGetSymbolAddress((void**)&p_whh,   g_whh);

    cudaFuncSetAttribute(mma_gemm_h1<0>,
                         cudaFuncAttributeMaxDynamicSharedMemorySize, SMEM_F_BYTES);
    cudaFuncSetAttribute(mma_gemm_h1<1>,
                         cudaFuncAttributeMaxDynamicSharedMemorySize, SMEM_F_BYTES);
    cudaFuncSetAttribute(lstm_persistent,
                         cudaFuncAttributeMaxDynamicSharedMemorySize, SMEM_F_BYTES);

    // prep
    reorder_pad_kernel<<<(M1 * KPAD + 255) / 256, 256>>>(inputs);
    transpose_wemb_kernel<<<(KPAD * HH + 255) / 256, 256>>>(W_emb);
    state_init_kernel<<<(BH + 255) / 256, 256>>>(h0, c0);
    conv_f16_kernel<<<(GG * HH + 255) / 256, 256>>>(W_ih, p_wih, GG * HH);
    conv_f16_kernel<<<(GG * HH + 255) / 256, 256>>>(W_hh, p_whh, GG * HH);
    bias_c_kernel<<<GG, 128>>>(W_ih, b_emb, b_ih, b_hh);

    // Wc = W_ih @ W_emb -> fp16 [4096, 128]
    mma_gemm_h1<1><<<dim3(KPAD / 128, GG / 64), 128, SMEM_F_BYTES>>>(
        p_wih, p_wembT, nullptr, p_wc, HH, KPAD);

    // gx = x @ Wc^T + bias_c -> fp16 [51200, 4096]
    mma_gemm_h1<1><<<dim3(GG / 128, M1 / 64), 128, SMEM_F_BYTES>>>(
        p_xh, p_wc, p_biasc, p_gx, KPAD, GG);

    // recurrence: ONE persistent kernel, 100 steps with grid barriers
    lstm_persistent<<<dim3(32, 8), NTHR, SMEM_F_BYTES>>>(p_gx, out);

    // final (h, c) after output — only if the harness buffer includes them
    if (out_size >= (AA + 2) * BH) {
        copy_hc_kernel<<<(BH + 255) / 256, 256>>>(out + (size_t)(AA - 1) * BH,
                                                  out + (size_t)AA * BH);
    }
}

// round 17
// speedup vs baseline: 1.3193x; 1.3193x over previous
#include <cuda_runtime.h>
#include <cuda_fp16.h>
#include <cstdint>
#include <cstddef>

// Problem constants
#define BB   512
#define AA   100
#define HH   1024
#define INN  77          // S*T = 7*11
#define KPAD 128         // padded input-feature dim
#define GG   4096        // 4*H
#define M1   (AA*BB)     // 51200
#define BH   (BB*HH)     // 524288

// ---------------- scratch (device globals; no allocation allowed) ----------------
__device__ __half g_xh    [(size_t)M1 * KPAD];   // reordered+padded inputs (fp16)
__device__ __half g_wembT [(size_t)KPAD * HH];   // W_emb^T padded (fp16)
__device__ __half g_wih_h [(size_t)GG * HH];     // W_ih fp16 (for Wc GEMM)
__device__ __half g_wc    [(size_t)GG * KPAD];   // Wc = W_ih @ W_emb  (fp16)
__device__ float  g_bias_c[GG];                  // W_ih@b_emb + b_ih + b_hh (fp32)
__device__ __half g_gx    [(size_t)M1 * GG];     // precomputed input gates (fp16)
__device__ __half g_gh    [(size_t)BB * GG];     // recurrent gates (fp16)
__device__ __half g_hf    [BH];                  // h state (fp16)
__device__ float  g_c     [BH];                  // c state (fp32)
__device__ __half g_whh   [(size_t)GG * HH];     // Whh fp16

// ================= PTX helpers (sm_80+ standard; NO arch-'a' features) =========
__device__ __forceinline__ uint32_t smem_u32(const void* p) {
    uint32_t a;
    asm("{ .reg .u64 t; cvta.to.shared.u64 t, %1; cvt.u32.u64 %0, t; }" : "=r"(a) : "l"(p));
    return a;
}
#define SMEM_SWIZZLE_128B(o) ((o) ^ (((o) >> 3) & 0x70))

__device__ __forceinline__ void cp_async16(uint32_t smem_addr, const void* gptr) {
    asm volatile("cp.async.cg.shared.global [%0], [%1], 16;"
                 :: "r"(smem_addr), "l"(gptr) : "memory");
}
#define CP_COMMIT() asm volatile("cp.async.commit_group;" ::: "memory")
#define CP_WAIT(n)  asm volatile("cp.async.wait_group %0;" :: "n"(n) : "memory")

__device__ __forceinline__ void ldsm_x4(uint32_t addr, uint32_t& r0, uint32_t& r1,
                                        uint32_t& r2, uint32_t& r3) {
    asm volatile("ldmatrix.sync.aligned.m8n8.x4.shared.b16 {%0,%1,%2,%3}, [%4];"
                 : "=r"(r0), "=r"(r1), "=r"(r2), "=r"(r3) : "r"(addr));
}

__device__ __forceinline__ void mma_f16(float* d, const uint32_t* a, const uint32_t* b) {
    asm volatile(
        "mma.sync.aligned.m16n8k16.row.col.f32.f16.f16.f32 "
        "{%0,%1,%2,%3}, {%4,%5,%6,%7}, {%8,%9}, {%0,%1,%2,%3};"
        : "+f"(d[0]), "+f"(d[1]), "+f"(d[2]), "+f"(d[3])
        : "r"(a[0]), "r"(a[1]), "r"(a[2]), "r"(a[3]), "r"(b[0]), "r"(b[1]));
}

// ================= prep kernels =================
__global__ void reorder_pad_kernel(const float* __restrict__ inputs) {
    int idx = blockIdx.x * blockDim.x + threadIdx.x;
    if (idx >= M1 * KPAD) return;
    int i = idx & (KPAD - 1);
    int r = idx >> 7;         // r = a*B + b
    int b = r % BB;
    int a = r / BB;
    float v = (i < INN) ? inputs[(size_t)b * (AA * INN) + (size_t)a * INN + i] : 0.f;
    g_xh[idx] = __float2half(v);
}

// W_emb [H,77] -> transposed+padded fp16 [128, H]
__global__ void transpose_wemb_kernel(const float* __restrict__ W_emb) {
    int idx = blockIdx.x * blockDim.x + threadIdx.x;
    if (idx >= KPAD * HH) return;
    int h = idx & (HH - 1);
    int n = idx >> 10;        // padded input-feature index
    float v = (n < INN) ? W_emb[(size_t)h * INN + n] : 0.f;
    g_wembT[idx] = __float2half(v);
}

// bias_c[j] = dot(W_ih[j,:], b_emb) + b_ih[j] + b_hh[j]; one 128-thr block per j
__global__ void bias_c_kernel(const float* __restrict__ W_ih, const float* __restrict__ b_emb,
                              const float* __restrict__ b_ih, const float* __restrict__ b_hh) {
    __shared__ float red[4];
    const int j = blockIdx.x;
    const int tid = threadIdx.x;
    float s = 0.f;
    for (int h = tid; h < HH; h += 128)
        s += W_ih[(size_t)j * HH + h] * b_emb[h];
    #pragma unroll
    for (int o = 16; o > 0; o >>= 1) s += __shfl_down_sync(0xFFFFFFFFu, s, o);
    if ((tid & 31) == 0) red[tid >> 5] = s;
    __syncthreads();
    if (tid == 0)
        g_bias_c[j] = red[0] + red[1] + red[2] + red[3] + b_ih[j] + b_hh[j];
}

__global__ void state_init_kernel(const float* __restrict__ h0, const float* __restrict__ c0) {
    int i = blockIdx.x * blockDim.x + threadIdx.x;
    if (i >= BH) return;
    g_hf[i] = __float2half(h0[i]);
    g_c[i] = c0[i];
}

__global__ void conv_f16_kernel(const float* __restrict__ src, __half* __restrict__ dst, int n) {
    int i = blockIdx.x * blockDim.x + threadIdx.x;
    if (i < n) dst[i] = __float2half(src[i]);
}

// ============== fp16 single-term GEMM, K-chunk 64 (R14/R15-proven) ============
// C[M,N] = A @ B^T (+bias); fp32 accum, single fp16 MMA term. CTA tile 64x128,
// 4 warps (warp tile 64x32), full 128B smem rows = 64 fp16 K-elems.
// 3-stage cp.async (prefetch-first order), 3 CTAs/SM.
// EPI: 0 = float C, 1 = __half C. bias (fp32) added before store when non-null.
#define HCHUNK 64
#define A_TILE 8192                     // 64 rows * 128B
#define B_TILE 16384                    // 128 rows * 128B
#define F_STAGE (A_TILE + B_TILE)       // 24 KB
#define F_NSTAGE 3
#define SMEM_F_BYTES (F_NSTAGE * F_STAGE + 1024)

template<int EPI>
__global__ __launch_bounds__(128, 3)
void mma_gemm_h1(const __half* __restrict__ A, const __half* __restrict__ B,
                 const float* __restrict__ bias, void* __restrict__ Cv,
                 int K, int ldc) {
    extern __shared__ char sm[];
    const uint32_t base = (smem_u32(sm) + 1023u) & ~1023u;
    const int tid = threadIdx.x;
    const int wid = tid >> 5, lane = tid & 31;
    const int wn = wid * 32;

    const __half* A_b = A + (size_t)blockIdx.y * 64 * K;
    const __half* B_b = B + (size_t)blockIdx.x * 128 * K;

    const int nchunk = K / HCHUNK;

    float acc[4][4][4];
    #pragma unroll
    for (int mi = 0; mi < 4; mi++)
        #pragma unroll
        for (int nj = 0; nj < 4; nj++)
            #pragma unroll
            for (int q = 0; q < 4; q++) acc[mi][nj][q] = 0.f;

    auto prefetch = [&](int ch) {
        const int kc = ch * HCHUNK;
        const uint32_t st = base + (uint32_t)(ch % F_NSTAGE) * F_STAGE;
        #pragma unroll
        for (int it = 0; it < 4; it++) {
            const int idx = it * 128 + tid;        // 0..511
            const int row = idx >> 3;
            const int g   = idx & 7;
            const uint32_t off = SMEM_SWIZZLE_128B((uint32_t)(row * 128 + g * 16));
            cp_async16(st + off, A_b + (size_t)row * K + kc + g * 8);
        }
        #pragma unroll
        for (int it = 0; it < 8; it++) {
            const int idx = it * 128 + tid;        // 0..1023
            const int row = idx >> 3;
            const int g   = idx & 7;
            const uint32_t off = SMEM_SWIZZLE_128B((uint32_t)(row * 128 + g * 16));
            cp_async16(st + A_TILE + off, B_b + (size_t)row * K + kc + g * 8);
        }
    };

    prefetch(0); CP_COMMIT();
    if (nchunk > 1) { prefetch(1); CP_COMMIT(); }

    const int tsel = lane >> 3, rin = lane & 7;

    for (int ch = 0; ch < nchunk; ch++) {
        if (ch + 2 < nchunk) {
            prefetch(ch + 2);
            CP_COMMIT();
            CP_WAIT(2);
        } else {
            CP_WAIT(0);
        }
        __syncthreads();

        const uint32_t st = base + (uint32_t)(ch % F_NSTAGE) * F_STAGE;
        const uint32_t sB = st + A_TILE;

        #pragma unroll
        for (int kk = 0; kk < HCHUNK; kk += 16) {
            const int colb = (kk + (tsel >> 1) * 8) * 2;   // 0..127 bytes
            uint32_t a[4][4];
            #pragma unroll
            for (int mi = 0; mi < 4; mi++) {
                const int row = mi * 16 + (tsel & 1) * 8 + rin;
                ldsm_x4(st + SMEM_SWIZZLE_128B((uint32_t)(row * 128 + colb)),
                        a[mi][0], a[mi][1], a[mi][2], a[mi][3]);
            }
            uint32_t b[4][2];
            #pragma unroll
            for (int g = 0; g < 2; g++) {
                const int row = wn + g * 16 + (tsel & 1) * 8 + rin;
                uint32_t r0, r1, r2, r3;
                ldsm_x4(sB + SMEM_SWIZZLE_128B((uint32_t)(row * 128 + colb)),
                        r0, r1, r2, r3);
                b[g * 2 + 0][0] = r0; b[g * 2 + 0][1] = r2;
                b[g * 2 + 1][0] = r1; b[g * 2 + 1][1] = r3;
            }
            #pragma unroll
            for (int mi = 0; mi < 4; mi++)
                #pragma unroll
                for (int nj = 0; nj < 4; nj++)
                    mma_f16(acc[mi][nj], a[mi], b[nj]);
        }
        __syncthreads();
    }

    // ---------------- epilogue ----------------
    const int r0 = lane >> 2;
    const int c0 = (lane & 3) * 2;
    #pragma unroll
    for (int mi = 0; mi < 4; mi++) {
        const size_t m0 = (size_t)blockIdx.y * 64 + mi * 16;
        #pragma unroll
        for (int nj = 0; nj < 4; nj++) {
            const int n = blockIdx.x * 128 + wn + nj * 8 + c0;
            float bx = 0.f, by = 0.f;
            if (bias) { bx = bias[n]; by = bias[n + 1]; }
            float vs[4] = {acc[mi][nj][0] + bx, acc[mi][nj][1] + by,
                           acc[mi][nj][2] + bx, acc[mi][nj][3] + by};
            if (EPI == 0) {
                float* C = (float*)Cv;
                *(float2*)(C + (m0 + r0) * (size_t)ldc + n) = make_float2(vs[0], vs[1]);
                *(float2*)(C + (m0 + r0 + 8) * (size_t)ldc + n) = make_float2(vs[2], vs[3]);
            } else {
                __half* C = (__half*)Cv;
                *(__half2*)(C + (m0 + r0) * (size_t)ldc + n) =
                    __floats2half2_rn(vs[0], vs[1]);
                *(__half2*)(C + (m0 + r0 + 8) * (size_t)ldc + n) =
                    __floats2half2_rn(vs[2], vs[3]);
            }
        }
    }
}

// -------- LSTM cell, vectorized by 2 (same fp32 math/rounding as R15) ----------
__global__ void lstm_cell_kernel_v2(const __half* __restrict__ gx, float* __restrict__ out_t) {
    const int p = blockIdx.x * blockDim.x + threadIdx.x;    // pair index
    if (p >= BH / 2) return;
    const int idx = p * 2;
    const int b = idx / HH, hh = idx % HH;
    const size_t gb = (size_t)b * GG;
    const __half2 x0 = *(const __half2*)(gx + gb + hh);
    const __half2 x1 = *(const __half2*)(gx + gb + HH + hh);
    const __half2 x2 = *(const __half2*)(gx + gb + 2 * HH + hh);
    const __half2 x3 = *(const __half2*)(gx + gb + 3 * HH + hh);
    const __half2 y0 = *(const __half2*)(g_gh + gb + hh);
    const __half2 y1 = *(const __half2*)(g_gh + gb + HH + hh);
    const __half2 y2 = *(const __half2*)(g_gh + gb + 2 * HH + hh);
    const __half2 y3 = *(const __half2*)(g_gh + gb + 3 * HH + hh);
    const float2 cc = *(const float2*)(g_c + idx);
    float hn0, hn1, cn0, cn1;
    {
        const float gi = __low2float(x0) + __low2float(y0);
        const float gf = __low2float(x1) + __low2float(y1);
        const float gg = __low2float(x2) + __low2float(y2);
        const float go = __low2float(x3) + __low2float(y3);
        const float i = 1.f / (1.f + expf(-gi));
        const float f = 1.f / (1.f + expf(-gf));
        const float g = tanhf(gg);
        const float o = 1.f / (1.f + expf(-go));
        cn0 = f * cc.x + i * g;
        hn0 = o * tanhf(cn0);
    }
    {
        const float gi = __high2float(x0) + __high2float(y0);
        const float gf = __high2float(x1) + __high2float(y1);
        const float gg = __high2float(x2) + __high2float(y2);
        const float go = __high2float(x3) + __high2float(y3);
        const float i = 1.f / (1.f + expf(-gi));
        const float f = 1.f / (1.f + expf(-gf));
        const float g = tanhf(gg);
        const float o = 1.f / (1.f + expf(-go));
        cn1 = f * cc.y + i * g;
        hn1 = o * tanhf(cn1);
    }
    *(float2*)(g_c + idx) = make_float2(cn0, cn1);
    *(__half2*)(g_hf + idx) = __floats2half2_rn(hn0, hn1);
    *(float2*)(out_t + idx) = make_float2(hn0, hn1);
}

__global__ void copy_hc_kernel(const float* __restrict__ last_h, float* __restrict__ dst) {
    int i = blockIdx.x * blockDim.x + threadIdx.x;
    if (i < BH) { dst[i] = last_h[i]; dst[BH + i] = g_c[i]; }
}

// ---------------- launch ----------------
extern "C" void kernel_launch(void* const* d_in, const int* in_sizes, int n_in,
                              void* d_out, int out_size) {
    const float* inputs = (const float*)d_in[0];
    const float* h0     = (const float*)d_in[1];
    const float* c0     = (const float*)d_in[2];
    const float* W_emb  = (const float*)d_in[3];
    const float* b_emb  = (const float*)d_in[4];
    const float* W_ih   = (const float*)d_in[5];
    const float* W_hh   = (const float*)d_in[6];
    const float* b_ih   = (const float*)d_in[7];
    const float* b_hh   = (const float*)d_in[8];
    float* out = (float*)d_out;

    // Real device addresses of scratch globals (host-shadow trap otherwise).
    float *p_biasc;
    __half *p_xh, *p_wembT, *p_wih, *p_wc, *p_gx, *p_gh, *p_hf, *p_whh;
    cudaGetSymbolAddress((void**)&p_xh,    g_xh);
    cudaGetSymbolAddress((void**)&p_wembT, g_wembT);
    cudaGetSymbolAddress((void**)&p_wih,   g_wih_h);
    cudaGetSymbolAddress((void**)&p_wc,    g_wc);
    cudaGetSymbolAddress((void**)&p_biasc, g_bias_c);
    cudaGetSymbolAddress((void**)&p_gx,    g_gx);
    cudaGetSymbolAddress((void**)&p_gh,    g_gh);
    cudaGetSymbolAddress((void**)&p_hf,    g_hf);
    cudaGetSymbolAddress((void**)&p_whh,   g_whh);

    cudaFuncSetAttribute(mma_gemm_h1<0>,
                         cudaFuncAttributeMaxDynamicSharedMemorySize, SMEM_F_BYTES);
    cudaFuncSetAttribute(mma_gemm_h1<1>,
                         cudaFuncAttributeMaxDynamicSharedMemorySize, SMEM_F_BYTES);

    // prep
    reorder_pad_kernel<<<(M1 * KPAD + 255) / 256, 256>>>(inputs);
    transpose_wemb_kernel<<<(KPAD * HH + 255) / 256, 256>>>(W_emb);
    state_init_kernel<<<(BH + 255) / 256, 256>>>(h0, c0);
    conv_f16_kernel<<<(GG * HH + 255) / 256, 256>>>(W_ih, p_wih, GG * HH);
    conv_f16_kernel<<<(GG * HH + 255) / 256, 256>>>(W_hh, p_whh, GG * HH);
    bias_c_kernel<<<GG, 128>>>(W_ih, b_emb, b_ih, b_hh);

    // Wc = W_ih @ W_emb -> fp16 [4096, 128]
    mma_gemm_h1<1><<<dim3(KPAD / 128, GG / 64), 128, SMEM_F_BYTES>>>(
        p_wih, p_wembT, nullptr, p_wc, HH, KPAD);

    // gx = x @ Wc^T + bias_c : [51200,128] @ [4096,128]^T -> fp16 [51200,4096]
    mma_gemm_h1<1><<<dim3(GG / 128, M1 / 64), 128, SMEM_F_BYTES>>>(
        p_xh, p_wc, p_biasc, p_gx, KPAD, GG);

    // recurrence: single-term fp16 GEMM (gh fp16) + vectorized cell per step
    for (int t = 0; t < AA; t++) {
        mma_gemm_h1<1><<<dim3(GG / 128, BB / 64), 128, SMEM_F_BYTES>>>(
            p_hf, p_whh, nullptr, p_gh, HH, GG);
        lstm_cell_kernel_v2<<<(BH / 2 + 255) / 256, 256>>>(
            p_gx + (size_t)t * BB * GG, out + (size_t)t * BH);
    }

    // final (h, c) after output — only if the harness buffer includes them
    if (out_size >= (AA + 2) * BH) {
        copy_hc_kernel<<<(BH + 255) / 256, 256>>>(out + (size_t)(AA - 1) * BH,
                                                  out + (size_t)AA * BH);
    }
}